// round 8
// baseline (speedup 1.0000x reference)
#include <cuda_runtime.h>
#include <cuda_bf16.h>
#include <cstdint>

// ----------------------------------------------------------------------------
// PhaseLinear, 2 kernels:
//  1) convert: fp32 X,W -> bf16 hi/lo planes in __device__ scratch
//  2) fused gemm: per CTA 64x64 (b,o) block; per K-chunk load A(hi/lo) once and
//     B(hi/lo) for all 4 control points; 4 accumulator sets; final in-register
//     blend out = sum_c coef[b,c]*(acc_c + bias[c,o]). cp.async 3-stage,
//     ldmatrix, mma.sync bf16 with 3-term hi/lo compensation.
// ----------------------------------------------------------------------------

#define BATCH 1024
#define INF   512
#define OUTF  512
#define NCP   4
#define NCAT  (NCP * OUTF)          // 2048

__device__ __nv_bfloat16 g_Xh[BATCH * INF], g_Xl[BATCH * INF];   // 1 MB each
__device__ __nv_bfloat16 g_Wh[NCAT * INF],  g_Wl[NCAT * INF];    // 2 MB each

// ---------------- helpers ----------------------------------------------------
__device__ __forceinline__ uint32_t smem_u32(const void* p) {
    uint32_t a;
    asm("{ .reg .u64 t; cvta.to.shared.u64 t, %1; cvt.u32.u64 %0, t; }"
        : "=r"(a) : "l"(p));
    return a;
}
__device__ __forceinline__ void split_pair(float x, float y, uint32_t& h, uint32_t& l) {
    asm("cvt.rn.bf16x2.f32 %0, %1, %2;" : "=r"(h) : "f"(y), "f"(x));  // {hi=y, lo=x}
    float hx = __uint_as_float(h << 16);
    float hy = __uint_as_float(h & 0xFFFF0000u);
    float rx = x - hx, ry = y - hy;
    asm("cvt.rn.bf16x2.f32 %0, %1, %2;" : "=r"(l) : "f"(ry), "f"(rx));
}
__device__ __forceinline__ void mma16816(float* d, const uint32_t* a, const uint32_t* b) {
    asm volatile(
        "mma.sync.aligned.m16n8k16.row.col.f32.bf16.bf16.f32 "
        "{%0,%1,%2,%3}, {%4,%5,%6,%7}, {%8,%9}, {%0,%1,%2,%3};"
        : "+f"(d[0]), "+f"(d[1]), "+f"(d[2]), "+f"(d[3])
        : "r"(a[0]), "r"(a[1]), "r"(a[2]), "r"(a[3]), "r"(b[0]), "r"(b[1]));
}
__device__ __forceinline__ void ldsm4(uint32_t* r, uint32_t addr) {
    asm volatile("ldmatrix.sync.aligned.m8n8.x4.shared.b16 {%0,%1,%2,%3}, [%4];"
        : "=r"(r[0]), "=r"(r[1]), "=r"(r[2]), "=r"(r[3]) : "r"(addr));
}
__device__ __forceinline__ void cpasync16(uint32_t dst, const void* src) {
    asm volatile("cp.async.cg.shared.global [%0], [%1], 16;" :: "r"(dst), "l"(src));
}

// ---------------- 1) convert --------------------------------------------------
__global__ void convert_kernel(const float* __restrict__ X, const float* __restrict__ W) {
    int i = blockIdx.x * blockDim.x + threadIdx.x;     // float4 index
    const int NX = BATCH * INF / 4;                    // 131072
    const int NW = NCAT * INF / 4;                     // 262144
    float4 v; uint2* dh; uint2* dl;
    if (i < NX) {
        v = ((const float4*)X)[i];
        dh = (uint2*)g_Xh + i; dl = (uint2*)g_Xl + i;
    } else {
        int j = i - NX;
        if (j >= NW) return;
        v = ((const float4*)W)[j];
        dh = (uint2*)g_Wh + j; dl = (uint2*)g_Wl + j;
    }
    uint2 hp, lp;
    split_pair(v.x, v.y, hp.x, lp.x);
    split_pair(v.z, v.w, hp.y, lp.y);
    *dh = hp; *dl = lp;
}

// ---------------- 2) fused GEMM ------------------------------------------------
// CTA: 64(m) x 64(n), BK=32, 16 K-chunks. Per stage 10 planes (Ah,Al,
// Bh[c0..3],Bl[c0..3]) of 64 rows x 80B (64B data + 16B pad) = 51200B.
#define ROWB    80
#define PLANE_B 5120
#define STAGE_B 51200
#define NSTAGE  3
#define NCHUNK  (INF / 32)     // 16
#define SMEM_DYN (NSTAGE * STAGE_B)

__global__ void __launch_bounds__(256, 1)
fused_gemm(const float* __restrict__ phase, const float* __restrict__ biases,
           float* __restrict__ out) {
    extern __shared__ __align__(128) char smem[];
    const uint32_t sbase = smem_u32(smem);
    __shared__ float coef_s[NCP][64];
    __shared__ float bias_s[NCP][64];

    const int tid  = threadIdx.x;
    const int wid  = tid >> 5;
    const int lane = tid & 31;
    const int g    = lane >> 2;
    const int t    = lane & 3;
    const int wm   = wid & 1;      // m-half: wm*32
    const int wn   = wid >> 1;     // n-quarter: wn*16
    const int mx   = blockIdx.x;   // 0..15 (64 batch rows)
    const int ny   = blockIdx.y;   // 0..7  (64 out cols)

    // ---- coef + bias tables ----
    if (tid < 64) {
        const float PI = 3.14159265358979323846f;
        float p = phase[mx * 64 + tid];
        float tt = (p < 1.5f * PI) ? (p / (1.5f * PI)) : ((p - 0.5f * PI) / (1.5f * PI));
        float t2 = tt * tt, t3 = t2 * tt;
        coef_s[0][tid] = t3 - 0.5f * t2;
        coef_s[1][tid] = 1.0f - 2.5f * t3;
        coef_s[2][tid] = 0.5f * t2 + 2.0f * t3;
        coef_s[3][tid] = -0.5f * t3;
    } else if (tid < 128) {
        int j = tid - 64;
        #pragma unroll
        for (int c = 0; c < NCP; c++)
            bias_s[c][j] = biases[c * OUTF + ny * 64 + j];
    }

    // ldmatrix lane addresses (byte offsets within a plane)
    const uint32_t a_lane = (((lane >> 3) & 1) * 8 + (lane & 7)) * ROWB
                          + (lane >> 4) * 16;
    const uint32_t b_lane = (((lane >> 4) & 1) * 8 + (lane & 7)) * ROWB
                          + ((lane >> 3) & 1) * 16;

    const __nv_bfloat16* xh = g_Xh + (size_t)(mx * 64) * INF;
    const __nv_bfloat16* xl = g_Xl + (size_t)(mx * 64) * INF;

    // fill one stage for K-chunk kc: 2560 cp.async x 16B, 10 per thread
    auto fill = [&](int stage, int kc) {
        #pragma unroll
        for (int i = 0; i < 10; i++) {
            int u     = i * 256 + tid;       // 0..2559
            int plane = u >> 8;              // 0..9
            int r     = (u >> 2) & 63;
            int seg   = u & 3;
            const __nv_bfloat16* src;
            if (plane == 0)      src = xh + (size_t)r * INF + kc * 32 + seg * 8;
            else if (plane == 1) src = xl + (size_t)r * INF + kc * 32 + seg * 8;
            else {
                int q = plane - 2;           // 0..7
                int c = q >> 1;
                const __nv_bfloat16* wb = (q & 1) ? g_Wl : g_Wh;
                src = wb + (size_t)(c * OUTF + ny * 64 + r) * INF + kc * 32 + seg * 8;
            }
            uint32_t dst = sbase + stage * STAGE_B + plane * PLANE_B
                         + r * ROWB + seg * 16;
            cpasync16(dst, src);
        }
        asm volatile("cp.async.commit_group;" ::: "memory");
    };

    // accumulators: 4 control points x 2 m-frags x 2 n-frags x 4
    float acc[NCP][2][2][4];
    #pragma unroll
    for (int c = 0; c < NCP; c++)
        #pragma unroll
        for (int mf = 0; mf < 2; mf++)
            #pragma unroll
            for (int nf = 0; nf < 2; nf++)
                #pragma unroll
                for (int r = 0; r < 4; r++) acc[c][mf][nf][r] = 0.f;

    fill(0, 0); fill(1, 1); fill(2, 2);

    for (int kc = 0; kc < NCHUNK; kc++) {
        if (kc <= NCHUNK - 4)
            asm volatile("cp.async.wait_group 2;" ::: "memory");
        else
            asm volatile("cp.async.wait_group 0;" ::: "memory");
        __syncthreads();

        const int st = kc % NSTAGE;
        const uint32_t sS = sbase + st * STAGE_B;

        #pragma unroll
        for (int ks = 0; ks < 2; ks++) {           // two k16 steps in BK=32
            const uint32_t ko = ks * 32;
            uint32_t ah[2][4], al[2][4];
            #pragma unroll
            for (int mf = 0; mf < 2; mf++) {
                uint32_t ra = (wm * 32 + mf * 16) * ROWB + a_lane + ko;
                ldsm4(ah[mf], sS + ra);
                ldsm4(al[mf], sS + PLANE_B + ra);
            }
            #pragma unroll
            for (int c = 0; c < NCP; c++) {
                const uint32_t pb = sS + (2 + 2 * c) * PLANE_B;   // Bh plane of c
                uint32_t rb = (wn * 16) * ROWB + b_lane + ko;
                uint32_t tmp[4];
                uint32_t bh[2][2], bl[2][2];
                ldsm4(tmp, pb + rb);
                bh[0][0] = tmp[0]; bh[0][1] = tmp[1];
                bh[1][0] = tmp[2]; bh[1][1] = tmp[3];
                ldsm4(tmp, pb + PLANE_B + rb);                    // Bl plane of c
                bl[0][0] = tmp[0]; bl[0][1] = tmp[1];
                bl[1][0] = tmp[2]; bl[1][1] = tmp[3];
                #pragma unroll
                for (int mf = 0; mf < 2; mf++)
                    #pragma unroll
                    for (int nf = 0; nf < 2; nf++) {
                        mma16816(acc[c][mf][nf], ah[mf], bh[nf]);
                        mma16816(acc[c][mf][nf], ah[mf], bl[nf]);
                        mma16816(acc[c][mf][nf], al[mf], bh[nf]);
                    }
            }
        }
        __syncthreads();
        if (kc + NSTAGE < NCHUNK) fill(st, kc + NSTAGE);
    }

    // ---- epilogue: blend with coef + bias, store 64x64 tile ----
    #pragma unroll
    for (int mf = 0; mf < 2; mf++) {
        const int rl0 = wm * 32 + mf * 16 + g;       // local rows rl0, rl0+8
        const int row0 = mx * 64 + rl0;
        #pragma unroll
        for (int nf = 0; nf < 2; nf++) {
            const int cl = wn * 16 + nf * 8 + 2 * t; // local cols cl, cl+1
            float r0 = 0.f, r1 = 0.f, r2 = 0.f, r3 = 0.f;
            #pragma unroll
            for (int c = 0; c < NCP; c++) {
                float cc0 = coef_s[c][rl0];
                float cc8 = coef_s[c][rl0 + 8];
                float b0  = bias_s[c][cl];
                float b1  = bias_s[c][cl + 1];
                r0 = fmaf(cc0, acc[c][mf][nf][0] + b0, r0);
                r1 = fmaf(cc0, acc[c][mf][nf][1] + b1, r1);
                r2 = fmaf(cc8, acc[c][mf][nf][2] + b0, r2);
                r3 = fmaf(cc8, acc[c][mf][nf][3] + b1, r3);
            }
            int col = ny * 64 + cl;
            *(float2*)(out + (size_t)row0 * OUTF + col)       = make_float2(r0, r1);
            *(float2*)(out + (size_t)(row0 + 8) * OUTF + col) = make_float2(r2, r3);
        }
    }
}

// ---------------- launch -------------------------------------------------------
extern "C" void kernel_launch(void* const* d_in, const int* in_sizes, int n_in,
                              void* d_out, int out_size) {
    const float* input   = (const float*)d_in[0];   // [1024,512]
    const float* phase   = (const float*)d_in[1];   // [1024]
    const float* weights = (const float*)d_in[2];   // [4,512,512]
    const float* biases  = (const float*)d_in[3];   // [4,512]
    float* out = (float*)d_out;                     // [1024,512]

    cudaFuncSetAttribute(fused_gemm,
                         cudaFuncAttributeMaxDynamicSharedMemorySize, SMEM_DYN);

    convert_kernel<<<1536, 256>>>(input, weights);

    dim3 grid(BATCH / 64, OUTF / 64);               // (16,8) = 128 CTAs
    fused_gemm<<<grid, 256, SMEM_DYN>>>(phase, biases, out);
}